// round 16
// baseline (speedup 1.0000x reference)
#include <cuda_runtime.h>

#define BS 8
#define CLS 4
#define CH 256
#define HH 128
#define WW 128
#define HW 16384
#define LL 19
#define LP 20    // padded L (scalar rows)
#define LD 40    // duplicated-pair row length
#define TK 256

typedef unsigned long long u64;

__device__ __forceinline__ u64 pack2(float lo, float hi) {
    u64 r; asm("mov.b64 %0, {%1, %2};" : "=l"(r) : "f"(lo), "f"(hi)); return r;
}
__device__ __forceinline__ void unpack2(u64 v, float& lo, float& hi) {
    asm("mov.b64 {%0, %1}, %2;" : "=f"(lo), "=f"(hi) : "l"(v));
}
__device__ __forceinline__ u64 fma2(u64 a, u64 b, u64 c) {
    u64 d; asm("fma.rn.f32x2 %0, %1, %2, %3;" : "=l"(d) : "l"(a), "l"(b), "l"(c)); return d;
}
__device__ __forceinline__ u64 mul2(u64 a, u64 b) {
    u64 d; asm("mul.rn.f32x2 %0, %1, %2;" : "=l"(d) : "l"(a), "l"(b)); return d;
}
__device__ __forceinline__ u64 add2(u64 a, u64 b) {
    u64 d; asm("add.rn.f32x2 %0, %1, %2;" : "=l"(d) : "l"(a), "l"(b)); return d;
}

// Static precomputes
__device__ float g_M[CH * CH];     // M[c'][c] = sum_t W2[t][c'] * W1[t][c]
__device__ float g_W3T[TK * CH];   // W3T[t][o] = W3[o][t]
// Per-batch rows, transposed + DUPLICATED pairs: [b][c][40], entry 2l and 2l+1 both = v[l]
__device__ float g_Ut2[BS * CH * LD];
__device__ float g_T3t2[BS * CH * LD];

// ---------------------------------------------------------------------------
// Kernel A0: M = W2^T * W1 (256 blocks, one M row each) + W3 transpose (16).
// ---------------------------------------------------------------------------
__global__ void prep_static_kernel(const float* __restrict__ W1,
                                   const float* __restrict__ W2,
                                   const float* __restrict__ W3) {
    const int bid = blockIdx.x;
    const int tid = threadIdx.x;  // 0..255
    if (bid < 256) {
        __shared__ float w2c[TK];
        w2c[tid] = W2[tid * TK + bid];   // column of W2 (one-time)
        __syncthreads();
        float acc = 0.f;
#pragma unroll 16
        for (int t = 0; t < TK; t++)
            acc += w2c[t] * W1[t * CH + tid];   // coalesced, 16 LDGs in flight
        g_M[bid * CH + tid] = acc;
    } else {
        const int tb = bid - 256;  // 0..15, 16 t-rows each
#pragma unroll
        for (int i = 0; i < 16; i++) {
            const int t = tb * 16 + i;
            g_W3T[t * CH + tid] = W3[tid * TK + t];  // write coalesced
        }
    }
}

// ---------------------------------------------------------------------------
// Kernel A: per-b U and t3 rows (transposed, duplicated). Grid (2, BS), 256 thr.
// ---------------------------------------------------------------------------
__global__ void precompute_kernel(const float* __restrict__ token_s,
                                  const float* __restrict__ b3) {
    const int half = blockIdx.x;
    const int b = blockIdx.y;
    const int tid = threadIdx.x;

    __shared__ float ts_t[TK * LP];  // ts transposed: [c'][l]

#pragma unroll
    for (int l = 0; l < LL; l++)
        ts_t[tid * LP + l] = token_s[(b * LL + l) * TK + tid];
    __syncthreads();

    const int wg = tid >> 7;             // 0 -> U, 1 -> t3
    const int c = half * 128 + (tid & 127);
    const float* __restrict__ Wp = (wg == 0) ? (g_M + c) : (g_W3T + c);

    float acc[LL];
#pragma unroll
    for (int l = 0; l < LL; l++) acc[l] = 0.f;

#pragma unroll 4
    for (int t = 0; t < TK; t++) {
        const float wv = Wp[t * CH];     // coalesced LDG
        const float4* tv = (const float4*)(ts_t + t * LP);
        float v[20];
        *(float4*)(v + 0)  = tv[0];
        *(float4*)(v + 4)  = tv[1];
        *(float4*)(v + 8)  = tv[2];
        *(float4*)(v + 12) = tv[3];
        *(float4*)(v + 16) = tv[4];
#pragma unroll
        for (int l = 0; l < LL; l++) acc[l] += v[l] * wv;
    }

    const float bias = (wg == 1) ? b3[c] : 0.f;
    float* dst = ((wg == 0) ? g_Ut2 : g_T3t2) + (b * CH + c) * LD;
#pragma unroll
    for (int l = 0; l < LL; l++) {
        const float v = acc[l] + bias;
        dst[2 * l] = v;
        dst[2 * l + 1] = v;
    }
    dst[38] = dst[39] = 0.f;  // pad pair (l=19)
}

// ---------------------------------------------------------------------------
// Kernel B: fused, f32x2 packed — each thread owns 2 consecutive pixels.
// Grid (BS, 64): block = 2 image rows, 128 threads. One 40KB smem buffer
// (duplicated-pair layout) reused: U (phase 1) then T3 (phase 3).
// ---------------------------------------------------------------------------
__global__ void __launch_bounds__(128, 4)
projector_main_kernel(const float* __restrict__ mask_t,
                      const float* __restrict__ fea_t,
                      float* __restrict__ out) {
    const int b = blockIdx.x;
    const int tile = blockIdx.y;     // rows 2*tile, 2*tile+1
    const int tid = threadIdx.x;

    __shared__ float sD[CH * LD];    // 40 KB, U-dup then T3-dup

    {
        const float4* src = (const float4*)(g_Ut2 + b * CH * LD);
        float4* dst = (float4*)sD;
#pragma unroll
        for (int i = 0; i < CH * LD / 4 / 128; i++)
            dst[tid + i * 128] = src[tid + i * 128];
    }
    __syncthreads();

    const int p0 = tile * 256 + tid * 2;   // 2 consecutive pixels (col even)
    const int row = p0 >> 7;
    const int col = p0 & 127;
    const int mh = row >> 1;
    const int mw = col >> 1;               // both pixels share this mask column

    // packed mask coefficients, pre-scaled by 0.25 (exact)
    u64 mm0, mm1, mm2, mm3;
    {
        const float* mp = mask_t + (b * CLS * 64 + mh) * 64 + mw;
        const float m0 = 0.25f * mp[0 * 64 * 64];
        const float m1 = 0.25f * mp[1 * 64 * 64];
        const float m2 = 0.25f * mp[2 * 64 * 64];
        const float m3 = 0.25f * mp[3 * 64 * 64];
        mm0 = pack2(m0, m0); mm1 = pack2(m1, m1);
        mm2 = pack2(m2, m2); mm3 = pack2(m3, m3);
    }

    const int fb = (b & 1) * 4;
    const u64* fp0 = (const u64*)(fea_t + (size_t)(fb + 0) * CH * HW + p0);
    const u64* fp1 = (const u64*)(fea_t + (size_t)(fb + 1) * CH * HW + p0);
    const u64* fp2 = (const u64*)(fea_t + (size_t)(fb + 2) * CH * HW + p0);
    const u64* fp3 = (const u64*)(fea_t + (size_t)(fb + 3) * CH * HW + p0);

    u64 a2[LL];
#pragma unroll
    for (int l = 0; l < LL; l++) a2[l] = 0ull;

    // ---- phase 1: a[l] += q * U[c][l], both pixels per packed op ----
#pragma unroll 2
    for (int c = 0; c < CH; c++) {
        const u64 f0 = fp0[c * (HW / 2)];
        const u64 f1 = fp1[c * (HW / 2)];
        const u64 f2 = fp2[c * (HW / 2)];
        const u64 f3 = fp3[c * (HW / 2)];
        u64 q = mul2(f0, mm0);
        q = fma2(f1, mm1, q);
        q = fma2(f2, mm2, q);
        q = fma2(f3, mm3, q);

        const ulonglong2* Dc = (const ulonglong2*)(sD + c * LD);
#pragma unroll
        for (int k = 0; k < 9; k++) {           // LDS.128 -> two packed {u,u}
            const ulonglong2 v = Dc[k];
            a2[2 * k]     = fma2(q, v.x, a2[2 * k]);
            a2[2 * k + 1] = fma2(q, v.y, a2[2 * k + 1]);
        }
        { const ulonglong2 v = Dc[9]; a2[18] = fma2(q, v.x, a2[18]); }
    }

    // ---- softmax over L per lane (logits a/16), zero where a == 0 exactly ----
    {
        float lo[LL], hi[LL];
#pragma unroll
        for (int l = 0; l < LL; l++) unpack2(a2[l], lo[l], hi[l]);
#define SOFTMAX(A)                                                        \
        {                                                                 \
            float e[LL];                                                  \
            float mx = A[0];                                              \
            _Pragma("unroll") for (int l = 1; l < LL; l++) mx = fmaxf(mx, A[l]); \
            float s = 0.f;                                                \
            _Pragma("unroll") for (int l = 0; l < LL; l++) { e[l] = __expf((A[l] - mx) * 0.0625f); s += e[l]; } \
            const float inv = 1.f / s;                                    \
            _Pragma("unroll") for (int l = 0; l < LL; l++) A[l] = (A[l] == 0.f) ? 0.f : e[l] * inv; \
        }
        SOFTMAX(lo)
        SOFTMAX(hi)
#undef SOFTMAX
#pragma unroll
        for (int l = 0; l < LL; l++) a2[l] = pack2(lo[l], hi[l]);
    }

    // swap smem buffer: U-dup -> T3-dup
    __syncthreads();
    {
        const float4* src = (const float4*)(g_T3t2 + b * CH * LD);
        float4* dst = (float4*)sD;
#pragma unroll
        for (int i = 0; i < CH * LD / 4 / 128; i++)
            dst[tid + i * 128] = src[tid + i * 128];
    }
    __syncthreads();

    // ---- phase 3: out[c] = sum_l w[l]*t3[c][l] + residual, packed ----
    const u64* rp = (const u64*)(fea_t + (size_t)b * CH * HW + p0);
    u64* op = (u64*)(out + (size_t)b * CH * HW + p0);
#pragma unroll 2
    for (int c = 0; c < CH; c++) {
        const ulonglong2* Dc = (const ulonglong2*)(sD + c * LD);
        u64 s;
        {
            const ulonglong2 v = Dc[0];
            s = mul2(a2[0], v.x);
            s = fma2(a2[1], v.y, s);
        }
#pragma unroll
        for (int k = 1; k < 9; k++) {
            const ulonglong2 v = Dc[k];
            s = fma2(a2[2 * k], v.x, s);
            s = fma2(a2[2 * k + 1], v.y, s);
        }
        { const ulonglong2 v = Dc[9]; s = fma2(a2[18], v.x, s); }
        op[c * (HW / 2)] = add2(s, rp[c * (HW / 2)]);
    }
}

extern "C" void kernel_launch(void* const* d_in, const int* in_sizes, int n_in,
                              void* d_out, int out_size) {
    const float* mask_t  = (const float*)d_in[0];
    const float* fea_t   = (const float*)d_in[1];
    const float* token_s = (const float*)d_in[2];
    const float* W1      = (const float*)d_in[3];
    const float* W2      = (const float*)d_in[4];
    const float* W3      = (const float*)d_in[5];
    const float* b3      = (const float*)d_in[6];

    prep_static_kernel<<<272, 256>>>(W1, W2, W3);
    precompute_kernel<<<dim3(2, BS), 256>>>(token_s, b3);
    projector_main_kernel<<<dim3(BS, 64), 128>>>(mask_t, fea_t, (float*)d_out);
}